// round 5
// baseline (speedup 1.0000x reference)
#include <cuda_runtime.h>
#include <cuda_fp16.h>
#include <math.h>
#include <stdint.h>

// B=8, S=256, N=256, C=64, NH=8, D=2048
// P (fp16): flat ((b*256+s)*256+n)*256+c ; n:[0,64)=q(norm) [64,128)=k(norm)
// [128,192)=vH [192,256)=vV
__device__ __half g_Ph[134217728];
__device__ __half g_AHm[4194304];   // [bh][s][t]
__device__ __half g_AVm[4194304];
__device__ __half g_Wh[16384];      // qkv_w fp16 [256][64]
__device__ __half g_PWh[4096];      // proj_w fp16 [64][64]

#define DINL __device__ __forceinline__

DINL uint32_t su32(const void* p) { return (uint32_t)__cvta_generic_to_shared(p); }

DINL void ldsm4(uint32_t r[4], const void* p) {
    asm volatile("ldmatrix.sync.aligned.m8n8.x4.shared.b16 {%0,%1,%2,%3},[%4];"
        : "=r"(r[0]), "=r"(r[1]), "=r"(r[2]), "=r"(r[3]) : "r"(su32(p)));
}
DINL void ldsm4t(uint32_t r[4], const void* p) {
    asm volatile("ldmatrix.sync.aligned.m8n8.x4.trans.shared.b16 {%0,%1,%2,%3},[%4];"
        : "=r"(r[0]), "=r"(r[1]), "=r"(r[2]), "=r"(r[3]) : "r"(su32(p)));
}
DINL void mma8(float c[4], const uint32_t a[4], uint32_t b0, uint32_t b1) {
    asm volatile("mma.sync.aligned.m16n8k16.row.col.f32.f16.f16.f32 "
        "{%0,%1,%2,%3},{%4,%5,%6,%7},{%8,%9},{%0,%1,%2,%3};"
        : "+f"(c[0]), "+f"(c[1]), "+f"(c[2]), "+f"(c[3])
        : "r"(a[0]), "r"(a[1]), "r"(a[2]), "r"(a[3]), "r"(b0), "r"(b1));
}
DINL void cpa16(void* s, const void* g) {
    asm volatile("cp.async.cg.shared.global [%0], [%1], 16;" :: "r"(su32(s)), "l"(g));
}
DINL void cpcommit() { asm volatile("cp.async.commit_group;"); }
DINL void cpwait0()  { asm volatile("cp.async.wait_group 0;"); }
DINL void cpwait1()  { asm volatile("cp.async.wait_group 1;"); }

// ---------------------------------------------------------------------------
// Kernel 0: one-time fp32 -> fp16 weight conversion.
// ---------------------------------------------------------------------------
__global__ void k_cvt(const float* __restrict__ qkv_w, const float* __restrict__ proj_w)
{
    int t = blockIdx.x * 256 + threadIdx.x;
    if (t < 16384) g_Wh[t]  = __float2half_rn(qkv_w[t]);
    if (t < 4096)  g_PWh[t] = __float2half_rn(proj_w[t]);
}

// ---------------------------------------------------------------------------
// Kernel 1: P = X @ W^T + bias, fused q/k 8-row-group L2 norm.
// grid(2048,2). 512 thr = 16 warps (4x4), warp tile 32x64.
// Staged smem -> coalesced global stores.
// ---------------------------------------------------------------------------
__global__ void __launch_bounds__(512, 1)
k_qkv(const float* __restrict__ x, const float* __restrict__ bias_)
{
    extern __shared__ __half sm[];
    __half* Xs = sm;                       // [128][72]
    __half* Ws = sm + 128 * 72;            // [256][72]
    __half* St = sm;                       // stage, reuse: [128][288]
    float*  bsh = (float*)((char*)sm + 73728);  // [256]
    float*  gss = bsh + 256;                    // [16]

    const int bs = blockIdx.x, half_ = blockIdx.y, n0 = half_ << 7;
    const int tid = threadIdx.x, lane = tid & 31, warp = tid >> 5;
    const int wr = warp >> 2, wc = warp & 3;

    { // X tile (128 x 64 fp32) -> fp16 smem
        int row = tid >> 2, k0 = (tid & 3) << 4;
        const float* src = x + ((size_t)bs * 256 + n0 + row) * 64 + k0;
        __half* dst = Xs + row * 72 + k0;
        #pragma unroll
        for (int i = 0; i < 4; i++) {
            float4 v = *(const float4*)(src + i * 4);
            dst[i*4+0] = __float2half_rn(v.x); dst[i*4+1] = __float2half_rn(v.y);
            dst[i*4+2] = __float2half_rn(v.z); dst[i*4+3] = __float2half_rn(v.w);
        }
    }
    { // W fp16 via cp.async
        #pragma unroll
        for (int i = 0; i < 4; i++) {
            int seg = tid * 4 + i;
            int row = seg >> 3, off = (seg & 7) << 3;
            cpa16(Ws + row * 72 + off, g_Wh + row * 64 + off);
        }
        cpcommit();
    }
    if (tid < 256) bsh[tid] = bias_[tid];
    if (tid < 16)  gss[tid] = 0.f;
    cpwait0();
    __syncthreads();

    float acc[2][8][4];
    #pragma unroll
    for (int mt = 0; mt < 2; mt++)
        #pragma unroll
        for (int nt = 0; nt < 8; nt++)
            #pragma unroll
            for (int q = 0; q < 4; q++) acc[mt][nt][q] = 0.f;

    #pragma unroll
    for (int kk = 0; kk < 4; kk++) {
        uint32_t af[2][4];
        #pragma unroll
        for (int mt = 0; mt < 2; mt++)
            ldsm4(af[mt], Xs + (wr*32 + mt*16 + (lane & 15)) * 72
                             + kk*16 + ((lane >> 4) << 3));
        #pragma unroll
        for (int g = 0; g < 4; g++) {
            uint32_t r[4];
            ldsm4(r, Ws + (wc*64 + g*16 + (lane & 15)) * 72
                        + kk*16 + ((lane >> 4) << 3));
            #pragma unroll
            for (int mt = 0; mt < 2; mt++) {
                mma8(acc[mt][2*g],   af[mt], r[0], r[2]);
                mma8(acc[mt][2*g+1], af[mt], r[1], r[3]);
            }
        }
    }

    // bias before norm
    #pragma unroll
    for (int nt = 0; nt < 8; nt++) {
        float b0 = bsh[wc*64 + nt*8 + 2*(lane & 3)];
        float b1 = bsh[wc*64 + nt*8 + 2*(lane & 3) + 1];
        #pragma unroll
        for (int mt = 0; mt < 2; mt++) {
            acc[mt][nt][0] += b0; acc[mt][nt][1] += b1;
            acc[mt][nt][2] += b0; acc[mt][nt][3] += b1;
        }
    }

    // q/k 8-row-group norms (half 0 only)
    if (half_ == 0) {
        #pragma unroll
        for (int mt = 0; mt < 2; mt++) {
            float p01 = 0.f, p23 = 0.f;
            #pragma unroll
            for (int nt = 0; nt < 8; nt++) {
                p01 += acc[mt][nt][0]*acc[mt][nt][0] + acc[mt][nt][1]*acc[mt][nt][1];
                p23 += acc[mt][nt][2]*acc[mt][nt][2] + acc[mt][nt][3]*acc[mt][nt][3];
            }
            #pragma unroll
            for (int off = 16; off > 0; off >>= 1) {
                p01 += __shfl_xor_sync(0xffffffffu, p01, off);
                p23 += __shfl_xor_sync(0xffffffffu, p23, off);
            }
            if (lane == 0) {
                atomicAdd(&gss[wr*4 + mt*2],     p01);
                atomicAdd(&gss[wr*4 + mt*2 + 1], p23);
            }
        }
    }
    __syncthreads();

    // stage scaled fp16 into smem (stride 288, 16B-unit swizzle)
    #pragma unroll
    for (int mt = 0; mt < 2; mt++) {
        float s01 = 1.f, s23 = 1.f;
        if (half_ == 0) {
            s01 = 1.f / fmaxf(sqrtf(gss[wr*4 + mt*2]),     1e-12f);
            s23 = 1.f / fmaxf(sqrtf(gss[wr*4 + mt*2 + 1]), 1e-12f);
        }
        int r0 = wr*32 + mt*16 + (lane >> 2);
        int xr = (r0 >> 1) & 1;
        #pragma unroll
        for (int nt = 0; nt < 8; nt++) {
            int c = wc*64 + nt*8 + 2*(lane & 3);
            int u = c >> 3, sub = c & 7;
            int up = ((u ^ xr) << 3) + sub;
            *(__half2*)(St + r0*288 + up) =
                __floats2half2_rn(acc[mt][nt][0]*s01, acc[mt][nt][1]*s01);
            *(__half2*)(St + (r0+8)*288 + up) =
                __floats2half2_rn(acc[mt][nt][2]*s23, acc[mt][nt][3]*s23);
        }
    }
    __syncthreads();

    { // coalesced global store
        int row = tid >> 2, q = tid & 3;
        int xr = (row >> 1) & 1;
        const __half* base = St + row * 288;
        __half* gp = g_Ph + ((size_t)bs * 256 + n0 + row) * 256;
        #pragma unroll
        for (int i = 0; i < 8; i++) {
            int u = q + 4*i;
            uint4 v = *(const uint4*)(base + ((u ^ xr) << 3));
            *(uint4*)(gp + (u << 3)) = v;
        }
    }
}

// ---------------------------------------------------------------------------
// Kernel 2: sim = Qn @ Kn^T per (b,h) + dual softmax (no max-shift; |sim|<=1).
// grid(64,2). 512 thr, warp tile 32x64 over 128x256. K=2048, chunk 64,
// cp.async double buffered.
// ---------------------------------------------------------------------------
__global__ void __launch_bounds__(512, 1)
k_attn(const float* __restrict__ t1g, const float* __restrict__ t2g)
{
    extern __shared__ __half sm2[];
    __half* Qs = sm2;                       // 2 x [128][88]
    __half* Ks = sm2 + 2 * 128 * 88;        // 2 x [256][88]
    float*  rs1 = (float*)(Ks + 2 * 256 * 88); // [128]
    float*  rs2 = rs1 + 128;                   // [128]

    const int bh = blockIdx.x, s0 = blockIdx.y << 7;
    const int b = bh >> 3, h = bh & 7;
    const __half* qb = g_Ph + (size_t)b * 16777216 + h * 2048;
    const __half* kb = qb + 16384;

    const int tid = threadIdx.x, lane = tid & 31, warp = tid >> 5;
    const int wr = warp >> 2, wc = warp & 3;

    if (tid < 128) { rs1[tid] = 0.f; rs2[tid] = 0.f; }

    auto loadQ = [&](int buf, int c) {
        int d0 = c * 64;
        #pragma unroll
        for (int i = 0; i < 2; i++) {
            int seg = tid * 2 + i, row = seg >> 3, off = (seg & 7) << 3;
            cpa16(Qs + buf*11264 + row*88 + off,
                  qb + (size_t)(s0 + row) * 65536 + d0 + off);
        }
    };
    auto loadK = [&](int buf, int c) {
        int d0 = c * 64;
        #pragma unroll
        for (int i = 0; i < 4; i++) {
            int seg = tid * 4 + i, row = seg >> 3, off = (seg & 7) << 3;
            cpa16(Ks + buf*22528 + row*88 + off,
                  kb + (size_t)row * 65536 + d0 + off);
        }
    };

    float acc[2][8][4];
    #pragma unroll
    for (int mt = 0; mt < 2; mt++)
        #pragma unroll
        for (int nt = 0; nt < 8; nt++)
            #pragma unroll
            for (int q = 0; q < 4; q++) acc[mt][nt][q] = 0.f;

    loadQ(0, 0); loadK(0, 0); cpcommit();
    for (int c = 0; c < 32; c++) {
        if (c < 31) { loadQ((c+1)&1, c+1); loadK((c+1)&1, c+1); cpcommit(); cpwait1(); }
        else cpwait0();
        __syncthreads();
        const __half* Q = Qs + (c & 1) * 11264;
        const __half* K = Ks + (c & 1) * 22528;
        #pragma unroll
        for (int kk = 0; kk < 4; kk++) {
            uint32_t af[2][4];
            #pragma unroll
            for (int mt = 0; mt < 2; mt++)
                ldsm4(af[mt], Q + (wr*32 + mt*16 + (lane & 15)) * 88
                                + kk*16 + ((lane >> 4) << 3));
            #pragma unroll
            for (int g = 0; g < 4; g++) {
                uint32_t r[4];
                ldsm4(r, K + (wc*64 + g*16 + (lane & 15)) * 88
                           + kk*16 + ((lane >> 4) << 3));
                #pragma unroll
                for (int mt = 0; mt < 2; mt++) {
                    mma8(acc[mt][2*g],   af[mt], r[0], r[2]);
                    mma8(acc[mt][2*g+1], af[mt], r[1], r[3]);
                }
            }
        }
        __syncthreads();
    }

    const float t1 = t1g[h], t2 = t2g[h];

    // pass 1: row sums of exp
    #pragma unroll
    for (int mt = 0; mt < 2; mt++) {
        float p1a = 0.f, p1b = 0.f, p2a = 0.f, p2b = 0.f;
        #pragma unroll
        for (int nt = 0; nt < 8; nt++) {
            p1a += __expf(acc[mt][nt][0]*t1) + __expf(acc[mt][nt][1]*t1);
            p1b += __expf(acc[mt][nt][2]*t1) + __expf(acc[mt][nt][3]*t1);
            p2a += __expf(acc[mt][nt][0]*t2) + __expf(acc[mt][nt][1]*t2);
            p2b += __expf(acc[mt][nt][2]*t2) + __expf(acc[mt][nt][3]*t2);
        }
        #pragma unroll
        for (int off = 1; off < 4; off <<= 1) {
            p1a += __shfl_xor_sync(0xffffffffu, p1a, off);
            p1b += __shfl_xor_sync(0xffffffffu, p1b, off);
            p2a += __shfl_xor_sync(0xffffffffu, p2a, off);
            p2b += __shfl_xor_sync(0xffffffffu, p2b, off);
        }
        if ((lane & 3) == 0) {
            int r0 = wr*32 + mt*16 + (lane >> 2);
            atomicAdd(&rs1[r0], p1a);     atomicAdd(&rs1[r0 + 8], p1b);
            atomicAdd(&rs2[r0], p2a);     atomicAdd(&rs2[r0 + 8], p2b);
        }
    }
    __syncthreads();

    // pass 2: normalize + store fp16
    #pragma unroll
    for (int mt = 0; mt < 2; mt++) {
        int r0 = wr*32 + mt*16 + (lane >> 2);
        float i1a = 1.f / rs1[r0], i1b = 1.f / rs1[r0 + 8];
        float i2a = 1.f / rs2[r0], i2b = 1.f / rs2[r0 + 8];
        #pragma unroll
        for (int nt = 0; nt < 8; nt++) {
            int col = wc*64 + nt*8 + 2*(lane & 3);
            size_t base = (size_t)bh * 65536 + (size_t)(s0 + r0) * 256 + col;
            *(__half2*)(g_AHm + base) = __floats2half2_rn(
                __expf(acc[mt][nt][0]*t1)*i1a, __expf(acc[mt][nt][1]*t1)*i1a);
            *(__half2*)(g_AHm + base + 2048) = __floats2half2_rn(
                __expf(acc[mt][nt][2]*t1)*i1b, __expf(acc[mt][nt][3]*t1)*i1b);
            *(__half2*)(g_AVm + base) = __floats2half2_rn(
                __expf(acc[mt][nt][0]*t2)*i2a, __expf(acc[mt][nt][1]*t2)*i2a);
            *(__half2*)(g_AVm + base + 2048) = __floats2half2_rn(
                __expf(acc[mt][nt][2]*t2)*i2b, __expf(acc[mt][nt][3]*t2)*i2b);
        }
    }
}

// ---------------------------------------------------------------------------
// Kernel 3 (v2): A_H/A_V resident in smem; loop dg=0..7 internally streaming
// V chunks; fused per-dg proj epilogue. grid(64,2) = (bh, s-half). 512 thr.
// smem: AHs[128][264] + AVs[128][264] + 2x(Vhs,Vvs)[32][264] + PW + pbs.
// ---------------------------------------------------------------------------
__global__ void __launch_bounds__(512, 1)
k_av(const float* __restrict__ pb, float* __restrict__ out)
{
    extern __shared__ __half sm3[];
    __half* AHs = sm3;                     // [128][264] = 33792
    __half* AVs = AHs + 33792;             // [128][264]
    __half* Vhs = AVs + 33792;             // 2 x [32][264] = 16896
    __half* Vvs = Vhs + 16896;             // 2 x [32][264]
    __half* PWs = Vvs + 16896;             // [64][72] = 4608
    float*  pbs = (float*)(PWs + 4608);    // [64]
    __half* XSs = Vhs;                     // epilogue reuse: [128][264] = 33792

    const int bh = blockIdx.x, b = bh >> 3, h = bh & 7;
    const int s0 = blockIdx.y << 7;

    const int tid = threadIdx.x, lane = tid & 31, warp = tid >> 5;
    const int wr = warp >> 2, wc = warp & 3;

    const __half* AHg = g_AHm + (size_t)bh * 65536 + (size_t)s0 * 256;
    const __half* AVg = g_AVm + (size_t)bh * 65536 + (size_t)s0 * 256;
    const __half* Pb  = g_Ph + (size_t)b * 16777216;

    { // resident A load: 4096 segs per matrix, 8 per thread each
        #pragma unroll
        for (int i = 0; i < 8; i++) {
            int seg = tid * 8 + i;
            int row = seg >> 5, off = (seg & 31) << 3;
            cpa16(AHs + row * 264 + off, AHg + (size_t)row * 256 + off);
            cpa16(AVs + row * 264 + off, AVg + (size_t)row * 256 + off);
        }
    }
    { // proj weight
        int row = tid >> 3, off = (tid & 7) << 3;
        cpa16(PWs + row * 72 + off, g_PWh + row * 64 + off);
    }
    if (tid < 64) pbs[tid] = pb[tid];
    cpcommit();
    cpwait0();
    __syncthreads();

    auto loadV = [&](int buf, int dg, int c) {
        int t0 = c * 32;
        const __half* vh = Pb + 32768 + h * 2048 + dg * 256;
        #pragma unroll
        for (int i = 0; i < 2; i++) {
            int sg = tid * 2 + i, row = sg >> 5, off = (sg & 31) << 3;
            cpa16(Vhs + buf*8448 + row*264 + off,
                  vh + (size_t)(t0 + row) * 65536 + off);
            int jj = off >> 6, cc = off & 63;
            cpa16(Vvs + buf*8448 + row*264 + off,
                  Pb + (size_t)(h*32 + dg*4 + jj) * 65536 + 49152
                     + (t0 + row) * 64 + cc);
        }
    };

    for (int dg = 0; dg < 8; dg++) {
        float acc[2][8][4];
        #pragma unroll
        for (int mt = 0; mt < 2; mt++)
            #pragma unroll
            for (int nt = 0; nt < 8; nt++)
                #pragma unroll
                for (int q = 0; q < 4; q++) acc[mt][nt][q] = 0.f;

        loadV(0, dg, 0); cpcommit();
        for (int c = 0; c < 8; c++) {
            if (c < 7) { loadV((c+1)&1, dg, c+1); cpcommit(); cpwait1(); }
            else cpwait0();
            __syncthreads();
            const int t0 = c * 32;
            const __half* VH = Vhs + (c & 1) * 8448;
            const __half* VV = Vvs + (c & 1) * 8448;
            #pragma unroll
            for (int kk = 0; kk < 2; kk++) {
                uint32_t aH[2][4], aV[2][4];
                #pragma unroll
                for (int mt = 0; mt < 2; mt++) {
                    ldsm4(aH[mt], AHs + (wr*32 + mt*16 + (lane & 15)) * 264
                                      + t0 + kk*16 + ((lane >> 4) << 3));
                    ldsm4(aV[mt], AVs + (wr*32 + mt*16 + (lane & 15)) * 264
                                      + t0 + kk*16 + ((lane >> 4) << 3));
                }
                #pragma unroll
                for (int g = 0; g < 4; g++) {
                    int D0 = wc*64 + g*16;
                    int trow = kk*16 + ((lane >> 4) << 3) + (lane & 7);
                    int dcol = D0 + (((lane >> 3) & 1) << 3);
                    uint32_t r[4];
                    ldsm4t(r, VH + trow*264 + dcol);
                    #pragma unroll
                    for (int mt = 0; mt < 2; mt++) {
                        mma8(acc[mt][2*g],   aH[mt], r[0], r[2]);
                        mma8(acc[mt][2*g+1], aH[mt], r[1], r[3]);
                    }
                    ldsm4t(r, VV + trow*264 + dcol);
                    #pragma unroll
                    for (int mt = 0; mt < 2; mt++) {
                        mma8(acc[mt][2*g],   aV[mt], r[0], r[2]);
                        mma8(acc[mt][2*g+1], aV[mt], r[1], r[3]);
                    }
                }
            }
            __syncthreads();
        }

        // stage xsum fp16 into V region (all V reads done after last sync)
        #pragma unroll
        for (int mt = 0; mt < 2; mt++) {
            int r0 = wr*32 + mt*16 + (lane >> 2);
            #pragma unroll
            for (int nt = 0; nt < 8; nt++) {
                int col = wc*64 + nt*8 + 2*(lane & 3);
                *(__half2*)(XSs + r0*264 + col) =
                    __floats2half2_rn(acc[mt][nt][0], acc[mt][nt][1]);
                *(__half2*)(XSs + (r0+8)*264 + col) =
                    __floats2half2_rn(acc[mt][nt][2], acc[mt][nt][3]);
            }
        }
        __syncthreads();

        float a2[2][8][4];
        #pragma unroll
        for (int mt = 0; mt < 2; mt++)
            #pragma unroll
            for (int nt = 0; nt < 8; nt++)
                #pragma unroll
                for (int q = 0; q < 4; q++) a2[mt][nt][q] = 0.f;

        #pragma unroll
        for (int kk = 0; kk < 4; kk++) {
            uint32_t af[2][4];
            #pragma unroll
            for (int mt = 0; mt < 2; mt++)
                ldsm4(af[mt], XSs + (wr*32 + mt*16 + (lane & 15)) * 264
                                  + wc*64 + kk*16 + ((lane >> 4) << 3));
            #pragma unroll
            for (int g = 0; g < 4; g++) {
                uint32_t r[4];
                ldsm4(r, PWs + (g*16 + (lane & 15)) * 72
                             + kk*16 + ((lane >> 4) << 3));
                #pragma unroll
                for (int mt = 0; mt < 2; mt++) {
                    mma8(a2[mt][2*g],   af[mt], r[0], r[2]);
                    mma8(a2[mt][2*g+1], af[mt], r[1], r[3]);
                }
            }
        }

        #pragma unroll
        for (int mt = 0; mt < 2; mt++) {
            int r0 = wr*32 + mt*16 + (lane >> 2);
            #pragma unroll
            for (int nt = 0; nt < 8; nt++) {
                int co = nt*8 + 2*(lane & 3);
                float b0 = pbs[co], b1 = pbs[co + 1];
                float* o0 = out + ((size_t)(b*256 + s0 + r0) * 256
                                   + h*32 + dg*4 + wc) * 64 + co;
                float* o1 = out + ((size_t)(b*256 + s0 + r0 + 8) * 256
                                   + h*32 + dg*4 + wc) * 64 + co;
                *(float2*)o0 = make_float2(a2[mt][nt][0] + b0, a2[mt][nt][1] + b1);
                *(float2*)o1 = make_float2(a2[mt][nt][2] + b0, a2[mt][nt][3] + b1);
            }
        }
        __syncthreads();   // XSs region freed before next dg's V loads
    }
}

// ---------------------------------------------------------------------------
extern "C" void kernel_launch(void* const* d_in, const int* in_sizes, int n_in,
                              void* d_out, int out_size)
{
    const float* x      = (const float*)d_in[0];
    const float* qkv_w  = (const float*)d_in[1];
    const float* qkv_b  = (const float*)d_in[2];
    const float* proj_w = (const float*)d_in[3];
    const float* proj_b = (const float*)d_in[4];
    const float* t1     = (const float*)d_in[5];
    const float* t2     = (const float*)d_in[6];
    float* out = (float*)d_out;

    const int smem1 = 73728 + 256*4 + 64;                           // ~74.8 KB
    const int smem2 = (2*128*88 + 2*256*88) * 2 + 256 * 4;          // ~136.2 KB
    const int smem3 = (33792*2 + 16896*2 + 4608) * 2 + 64 * 4;      // ~212.2 KB

    cudaFuncSetAttribute((const void*)k_qkv,
                         cudaFuncAttributeMaxDynamicSharedMemorySize, smem1);
    cudaFuncSetAttribute((const void*)k_attn,
                         cudaFuncAttributeMaxDynamicSharedMemorySize, smem2);
    cudaFuncSetAttribute((const void*)k_av,
                         cudaFuncAttributeMaxDynamicSharedMemorySize, smem3);

    k_cvt <<<64, 256>>>(qkv_w, proj_w);
    k_qkv <<<dim3(2048, 2), 512, smem1>>>(x, qkv_b);
    k_attn<<<dim3(64, 2),   512, smem2>>>(t1, t2);
    k_av  <<<dim3(64, 2),   512, smem3>>>(proj_b, out);
}

// round 6
// speedup vs baseline: 1.0250x; 1.0250x over previous
#include <cuda_runtime.h>
#include <cuda_fp16.h>
#include <math.h>
#include <stdint.h>

// B=8, S=256, N=256, C=64, NH=8, D=2048
// P (fp16): flat ((b*256+s)*256+n)*256+c ; n:[0,64)=q(norm) [64,128)=k(norm)
// [128,192)=vH [192,256)=vV
__device__ __half g_Ph[134217728];
__device__ __half g_AHm[4194304];   // [bh][s][t]
__device__ __half g_AVm[4194304];
__device__ __half g_Wh[16384];      // qkv_w fp16 [256][64]
__device__ __half g_PWh[4096];      // proj_w fp16 [64][64]

#define DINL __device__ __forceinline__

DINL uint32_t su32(const void* p) { return (uint32_t)__cvta_generic_to_shared(p); }

DINL void ldsm4(uint32_t r[4], const void* p) {
    asm volatile("ldmatrix.sync.aligned.m8n8.x4.shared.b16 {%0,%1,%2,%3},[%4];"
        : "=r"(r[0]), "=r"(r[1]), "=r"(r[2]), "=r"(r[3]) : "r"(su32(p)));
}
DINL void ldsm4t(uint32_t r[4], const void* p) {
    asm volatile("ldmatrix.sync.aligned.m8n8.x4.trans.shared.b16 {%0,%1,%2,%3},[%4];"
        : "=r"(r[0]), "=r"(r[1]), "=r"(r[2]), "=r"(r[3]) : "r"(su32(p)));
}
DINL void mma8(float c[4], const uint32_t a[4], uint32_t b0, uint32_t b1) {
    asm volatile("mma.sync.aligned.m16n8k16.row.col.f32.f16.f16.f32 "
        "{%0,%1,%2,%3},{%4,%5,%6,%7},{%8,%9},{%0,%1,%2,%3};"
        : "+f"(c[0]), "+f"(c[1]), "+f"(c[2]), "+f"(c[3])
        : "r"(a[0]), "r"(a[1]), "r"(a[2]), "r"(a[3]), "r"(b0), "r"(b1));
}
DINL void cpa16(void* s, const void* g) {
    asm volatile("cp.async.cg.shared.global [%0], [%1], 16;" :: "r"(su32(s)), "l"(g));
}
DINL void cpcommit() { asm volatile("cp.async.commit_group;"); }
DINL void cpwait0()  { asm volatile("cp.async.wait_group 0;"); }
DINL void cpwait1()  { asm volatile("cp.async.wait_group 1;"); }

// ---------------------------------------------------------------------------
// Kernel 0: one-time fp32 -> fp16 weight conversion.
// ---------------------------------------------------------------------------
__global__ void k_cvt(const float* __restrict__ qkv_w, const float* __restrict__ proj_w)
{
    int t = blockIdx.x * 256 + threadIdx.x;
    if (t < 16384) g_Wh[t]  = __float2half_rn(qkv_w[t]);
    if (t < 4096)  g_PWh[t] = __float2half_rn(proj_w[t]);
}

// ---------------------------------------------------------------------------
// Kernel 1: P = X @ W^T + bias, fused q/k 8-row-group L2 norm.
// grid(2048,2). 512 thr = 16 warps (4x4), warp tile 32x64.
// Staged smem -> coalesced global stores. (unchanged from R4)
// ---------------------------------------------------------------------------
__global__ void __launch_bounds__(512, 1)
k_qkv(const float* __restrict__ x, const float* __restrict__ bias_)
{
    extern __shared__ __half sm[];
    __half* Xs = sm;                       // [128][72]
    __half* Ws = sm + 128 * 72;            // [256][72]
    __half* St = sm;                       // stage, reuse: [128][288]
    float*  bsh = (float*)((char*)sm + 73728);  // [256]
    float*  gss = bsh + 256;                    // [16]

    const int bs = blockIdx.x, half_ = blockIdx.y, n0 = half_ << 7;
    const int tid = threadIdx.x, lane = tid & 31, warp = tid >> 5;
    const int wr = warp >> 2, wc = warp & 3;

    { // X tile (128 x 64 fp32) -> fp16 smem
        int row = tid >> 2, k0 = (tid & 3) << 4;
        const float* src = x + ((size_t)bs * 256 + n0 + row) * 64 + k0;
        __half* dst = Xs + row * 72 + k0;
        #pragma unroll
        for (int i = 0; i < 4; i++) {
            float4 v = *(const float4*)(src + i * 4);
            dst[i*4+0] = __float2half_rn(v.x); dst[i*4+1] = __float2half_rn(v.y);
            dst[i*4+2] = __float2half_rn(v.z); dst[i*4+3] = __float2half_rn(v.w);
        }
    }
    { // W fp16 via cp.async
        #pragma unroll
        for (int i = 0; i < 4; i++) {
            int seg = tid * 4 + i;
            int row = seg >> 3, off = (seg & 7) << 3;
            cpa16(Ws + row * 72 + off, g_Wh + row * 64 + off);
        }
        cpcommit();
    }
    if (tid < 256) bsh[tid] = bias_[tid];
    if (tid < 16)  gss[tid] = 0.f;
    cpwait0();
    __syncthreads();

    float acc[2][8][4];
    #pragma unroll
    for (int mt = 0; mt < 2; mt++)
        #pragma unroll
        for (int nt = 0; nt < 8; nt++)
            #pragma unroll
            for (int q = 0; q < 4; q++) acc[mt][nt][q] = 0.f;

    #pragma unroll
    for (int kk = 0; kk < 4; kk++) {
        uint32_t af[2][4];
        #pragma unroll
        for (int mt = 0; mt < 2; mt++)
            ldsm4(af[mt], Xs + (wr*32 + mt*16 + (lane & 15)) * 72
                             + kk*16 + ((lane >> 4) << 3));
        #pragma unroll
        for (int g = 0; g < 4; g++) {
            uint32_t r[4];
            ldsm4(r, Ws + (wc*64 + g*16 + (lane & 15)) * 72
                        + kk*16 + ((lane >> 4) << 3));
            #pragma unroll
            for (int mt = 0; mt < 2; mt++) {
                mma8(acc[mt][2*g],   af[mt], r[0], r[2]);
                mma8(acc[mt][2*g+1], af[mt], r[1], r[3]);
            }
        }
    }

    // bias before norm
    #pragma unroll
    for (int nt = 0; nt < 8; nt++) {
        float b0 = bsh[wc*64 + nt*8 + 2*(lane & 3)];
        float b1 = bsh[wc*64 + nt*8 + 2*(lane & 3) + 1];
        #pragma unroll
        for (int mt = 0; mt < 2; mt++) {
            acc[mt][nt][0] += b0; acc[mt][nt][1] += b1;
            acc[mt][nt][2] += b0; acc[mt][nt][3] += b1;
        }
    }

    // q/k 8-row-group norms (half 0 only)
    if (half_ == 0) {
        #pragma unroll
        for (int mt = 0; mt < 2; mt++) {
            float p01 = 0.f, p23 = 0.f;
            #pragma unroll
            for (int nt = 0; nt < 8; nt++) {
                p01 += acc[mt][nt][0]*acc[mt][nt][0] + acc[mt][nt][1]*acc[mt][nt][1];
                p23 += acc[mt][nt][2]*acc[mt][nt][2] + acc[mt][nt][3]*acc[mt][nt][3];
            }
            #pragma unroll
            for (int off = 16; off > 0; off >>= 1) {
                p01 += __shfl_xor_sync(0xffffffffu, p01, off);
                p23 += __shfl_xor_sync(0xffffffffu, p23, off);
            }
            if (lane == 0) {
                atomicAdd(&gss[wr*4 + mt*2],     p01);
                atomicAdd(&gss[wr*4 + mt*2 + 1], p23);
            }
        }
    }
    __syncthreads();

    // stage scaled fp16 into smem (stride 288, 16B-unit swizzle)
    #pragma unroll
    for (int mt = 0; mt < 2; mt++) {
        float s01 = 1.f, s23 = 1.f;
        if (half_ == 0) {
            s01 = 1.f / fmaxf(sqrtf(gss[wr*4 + mt*2]),     1e-12f);
            s23 = 1.f / fmaxf(sqrtf(gss[wr*4 + mt*2 + 1]), 1e-12f);
        }
        int r0 = wr*32 + mt*16 + (lane >> 2);
        int xr = (r0 >> 1) & 1;
        #pragma unroll
        for (int nt = 0; nt < 8; nt++) {
            int c = wc*64 + nt*8 + 2*(lane & 3);
            int u = c >> 3, sub = c & 7;
            int up = ((u ^ xr) << 3) + sub;
            *(__half2*)(St + r0*288 + up) =
                __floats2half2_rn(acc[mt][nt][0]*s01, acc[mt][nt][1]*s01);
            *(__half2*)(St + (r0+8)*288 + up) =
                __floats2half2_rn(acc[mt][nt][2]*s23, acc[mt][nt][3]*s23);
        }
    }
    __syncthreads();

    { // coalesced global store
        int row = tid >> 2, q = tid & 3;
        int xr = (row >> 1) & 1;
        const __half* base = St + row * 288;
        __half* gp = g_Ph + ((size_t)bs * 256 + n0 + row) * 256;
        #pragma unroll
        for (int i = 0; i < 8; i++) {
            int u = q + 4*i;
            uint4 v = *(const uint4*)(base + ((u ^ xr) << 3));
            *(uint4*)(gp + (u << 3)) = v;
        }
    }
}

// ---------------------------------------------------------------------------
// Kernel 2: sim = Qn @ Kn^T per (b,h) + dual softmax.
// grid(64,2). 512 thr, warp tile 32x64 over 128x256. K=2048, chunk 64,
// 3-stage cp.async pipeline, ONE sync per chunk.
// ---------------------------------------------------------------------------
__global__ void __launch_bounds__(512, 1)
k_attn(const float* __restrict__ t1g, const float* __restrict__ t2g)
{
    extern __shared__ __half sm2[];
    __half* Qs = sm2;                          // 3 x [128][88] = 3*11264
    __half* Ks = sm2 + 3 * 11264;              // 3 x [256][88] = 3*22528
    float*  rs1 = (float*)(Ks + 3 * 22528);    // [128]
    float*  rs2 = rs1 + 128;                   // [128]

    const int bh = blockIdx.x, s0 = blockIdx.y << 7;
    const int b = bh >> 3, h = bh & 7;
    const __half* qb = g_Ph + (size_t)b * 16777216 + h * 2048;
    const __half* kb = qb + 16384;

    const int tid = threadIdx.x, lane = tid & 31, warp = tid >> 5;
    const int wr = warp >> 2, wc = warp & 3;

    if (tid < 128) { rs1[tid] = 0.f; rs2[tid] = 0.f; }

    auto loadQK = [&](int buf, int c) {
        int d0 = c * 64;
        #pragma unroll
        for (int i = 0; i < 2; i++) {
            int seg = tid * 2 + i, row = seg >> 3, off = (seg & 7) << 3;
            cpa16(Qs + buf*11264 + row*88 + off,
                  qb + (size_t)(s0 + row) * 65536 + d0 + off);
        }
        #pragma unroll
        for (int i = 0; i < 4; i++) {
            int seg = tid * 4 + i, row = seg >> 3, off = (seg & 7) << 3;
            cpa16(Ks + buf*22528 + row*88 + off,
                  kb + (size_t)row * 65536 + d0 + off);
        }
        cpcommit();
    };

    float acc[2][8][4];
    #pragma unroll
    for (int mt = 0; mt < 2; mt++)
        #pragma unroll
        for (int nt = 0; nt < 8; nt++)
            #pragma unroll
            for (int q = 0; q < 4; q++) acc[mt][nt][q] = 0.f;

    loadQK(0, 0);
    loadQK(1, 1);
    for (int c = 0; c < 32; c++) {
        if (c < 31) cpwait1(); else cpwait0();
        __syncthreads();
        if (c + 2 < 32) loadQK((c + 2) % 3, c + 2);
        const int st = c % 3;
        const __half* Q = Qs + st * 11264;
        const __half* K = Ks + st * 22528;
        #pragma unroll
        for (int kk = 0; kk < 4; kk++) {
            uint32_t af[2][4];
            #pragma unroll
            for (int mt = 0; mt < 2; mt++)
                ldsm4(af[mt], Q + (wr*32 + mt*16 + (lane & 15)) * 88
                                + kk*16 + ((lane >> 4) << 3));
            #pragma unroll
            for (int g = 0; g < 4; g++) {
                uint32_t r[4];
                ldsm4(r, K + (wc*64 + g*16 + (lane & 15)) * 88
                           + kk*16 + ((lane >> 4) << 3));
                #pragma unroll
                for (int mt = 0; mt < 2; mt++) {
                    mma8(acc[mt][2*g],   af[mt], r[0], r[2]);
                    mma8(acc[mt][2*g+1], af[mt], r[1], r[3]);
                }
            }
        }
    }
    __syncthreads();

    const float t1 = t1g[h], t2 = t2g[h];

    // pass 1: row sums of exp
    #pragma unroll
    for (int mt = 0; mt < 2; mt++) {
        float p1a = 0.f, p1b = 0.f, p2a = 0.f, p2b = 0.f;
        #pragma unroll
        for (int nt = 0; nt < 8; nt++) {
            p1a += __expf(acc[mt][nt][0]*t1) + __expf(acc[mt][nt][1]*t1);
            p1b += __expf(acc[mt][nt][2]*t1) + __expf(acc[mt][nt][3]*t1);
            p2a += __expf(acc[mt][nt][0]*t2) + __expf(acc[mt][nt][1]*t2);
            p2b += __expf(acc[mt][nt][2]*t2) + __expf(acc[mt][nt][3]*t2);
        }
        #pragma unroll
        for (int off = 1; off < 4; off <<= 1) {
            p1a += __shfl_xor_sync(0xffffffffu, p1a, off);
            p1b += __shfl_xor_sync(0xffffffffu, p1b, off);
            p2a += __shfl_xor_sync(0xffffffffu, p2a, off);
            p2b += __shfl_xor_sync(0xffffffffu, p2b, off);
        }
        if ((lane & 3) == 0) {
            int r0 = wr*32 + mt*16 + (lane >> 2);
            atomicAdd(&rs1[r0], p1a);     atomicAdd(&rs1[r0 + 8], p1b);
            atomicAdd(&rs2[r0], p2a);     atomicAdd(&rs2[r0 + 8], p2b);
        }
    }
    __syncthreads();

    // pass 2: normalize + store fp16
    #pragma unroll
    for (int mt = 0; mt < 2; mt++) {
        int r0 = wr*32 + mt*16 + (lane >> 2);
        float i1a = 1.f / rs1[r0], i1b = 1.f / rs1[r0 + 8];
        float i2a = 1.f / rs2[r0], i2b = 1.f / rs2[r0 + 8];
        #pragma unroll
        for (int nt = 0; nt < 8; nt++) {
            int col = wc*64 + nt*8 + 2*(lane & 3);
            size_t base = (size_t)bh * 65536 + (size_t)(s0 + r0) * 256 + col;
            *(__half2*)(g_AHm + base) = __floats2half2_rn(
                __expf(acc[mt][nt][0]*t1)*i1a, __expf(acc[mt][nt][1]*t1)*i1a);
            *(__half2*)(g_AHm + base + 2048) = __floats2half2_rn(
                __expf(acc[mt][nt][2]*t1)*i1b, __expf(acc[mt][nt][3]*t1)*i1b);
            *(__half2*)(g_AVm + base) = __floats2half2_rn(
                __expf(acc[mt][nt][0]*t2)*i2a, __expf(acc[mt][nt][1]*t2)*i2a);
            *(__half2*)(g_AVm + base + 2048) = __floats2half2_rn(
                __expf(acc[mt][nt][2]*t2)*i2b, __expf(acc[mt][nt][3]*t2)*i2b);
        }
    }
}

// ---------------------------------------------------------------------------
// Kernel 3 (v3): grid(64,16) streaming layout (R4 config), 3-stage cp.async
// pipeline, one sync per chunk, fused proj epilogue.
// ---------------------------------------------------------------------------
__global__ void __launch_bounds__(512, 1)
k_av(const float* __restrict__ pb, float* __restrict__ out)
{
    extern __shared__ __half sm3[];
    __half* AHs = sm3;                     // 3 x [128][40] = 3*5120
    __half* AVs = AHs + 3 * 5120;          // 3 x [128][40]
    __half* Vhs = AVs + 3 * 5120;          // 3 x [32][264] = 3*8448
    __half* Vvs = Vhs + 3 * 8448;          // 3 x [32][264]
    __half* PWs = Vvs + 3 * 8448;          // [64][72]
    float*  pbs = (float*)(PWs + 64 * 72); // [64]
    __half* XSs = Vhs;                     // epilogue reuse: [128][264] = 33792
                                           // (Vhs+Vvs contiguous = 50688, fits)

    const int bh = blockIdx.x, b = bh >> 3, h = bh & 7;
    const int tile = blockIdx.y;
    const int s0 = (tile & 1) << 7, dg = tile >> 1;
    const int d0 = dg << 8, j0 = dg << 2;

    const int tid = threadIdx.x, lane = tid & 31, warp = tid >> 5;
    const int wr = warp >> 2, wc = warp & 3;

    const __half* AHg = g_AHm + (size_t)bh * 65536 + (size_t)s0 * 256;
    const __half* AVg = g_AVm + (size_t)bh * 65536 + (size_t)s0 * 256;
    const __half* vh  = g_Ph + (size_t)b * 16777216 + 32768 + h * 2048 + d0;
    const __half* vv  = g_Ph + (size_t)b * 16777216 + (size_t)(h*32 + j0) * 65536 + 49152;

    { // proj weight fp16 via cp.async (group 0, waited with first chunk)
        int row = tid >> 3, off = (tid & 7) << 3;
        cpa16(PWs + row * 72 + off, g_PWh + row * 64 + off);
    }
    if (tid < 64) pbs[tid] = pb[tid];

    auto loadAV = [&](int buf, int c) {
        int t0 = c * 32;
        {
            int row = tid >> 2, off = (tid & 3) << 3;
            cpa16(AHs + buf*5120 + row*40 + off, AHg + (size_t)row * 256 + t0 + off);
            cpa16(AVs + buf*5120 + row*40 + off, AVg + (size_t)row * 256 + t0 + off);
        }
        #pragma unroll
        for (int i = 0; i < 2; i++) {
            int sg = tid * 2 + i, row = sg >> 5, off = (sg & 31) << 3;
            cpa16(Vhs + buf*8448 + row*264 + off,
                  vh + (size_t)(t0 + row) * 65536 + off);
            int jj = off >> 6, cc = off & 63;
            cpa16(Vvs + buf*8448 + row*264 + off,
                  vv + (size_t)jj * 65536 + (t0 + row) * 64 + cc);
        }
        cpcommit();
    };

    float acc[2][8][4];
    #pragma unroll
    for (int mt = 0; mt < 2; mt++)
        #pragma unroll
        for (int nt = 0; nt < 8; nt++)
            #pragma unroll
            for (int q = 0; q < 4; q++) acc[mt][nt][q] = 0.f;

    loadAV(0, 0);      // group 0 also carries PW
    loadAV(1, 1);
    for (int c = 0; c < 8; c++) {
        if (c < 7) cpwait1(); else cpwait0();
        __syncthreads();
        if (c + 2 < 8) loadAV((c + 2) % 3, c + 2);
        const int st = c % 3;
        const __half* AH = AHs + st * 5120;
        const __half* AV = AVs + st * 5120;
        const __half* VH = Vhs + st * 8448;
        const __half* VV = Vvs + st * 8448;
        #pragma unroll
        for (int kk = 0; kk < 2; kk++) {
            uint32_t aH[2][4], aV[2][4];
            #pragma unroll
            for (int mt = 0; mt < 2; mt++) {
                ldsm4(aH[mt], AH + (wr*32 + mt*16 + (lane & 15)) * 40
                                 + kk*16 + ((lane >> 4) << 3));
                ldsm4(aV[mt], AV + (wr*32 + mt*16 + (lane & 15)) * 40
                                 + kk*16 + ((lane >> 4) << 3));
            }
            #pragma unroll
            for (int g = 0; g < 4; g++) {
                int D0 = wc*64 + g*16;
                int trow = kk*16 + ((lane >> 4) << 3) + (lane & 7);
                int dcol = D0 + (((lane >> 3) & 1) << 3);
                uint32_t r[4];
                ldsm4t(r, VH + trow*264 + dcol);
                #pragma unroll
                for (int mt = 0; mt < 2; mt++) {
                    mma8(acc[mt][2*g],   aH[mt], r[0], r[2]);
                    mma8(acc[mt][2*g+1], aH[mt], r[1], r[3]);
                }
                ldsm4t(r, VV + trow*264 + dcol);
                #pragma unroll
                for (int mt = 0; mt < 2; mt++) {
                    mma8(acc[mt][2*g],   aV[mt], r[0], r[2]);
                    mma8(acc[mt][2*g+1], aV[mt], r[1], r[3]);
                }
            }
        }
    }
    __syncthreads();   // all MMA reads done before XSs overwrite

    // stage xsum fp16 -> smem (V region), then proj MMA
    #pragma unroll
    for (int mt = 0; mt < 2; mt++) {
        int r0 = wr*32 + mt*16 + (lane >> 2);
        #pragma unroll
        for (int nt = 0; nt < 8; nt++) {
            int col = wc*64 + nt*8 + 2*(lane & 3);
            *(__half2*)(XSs + r0*264 + col) =
                __floats2half2_rn(acc[mt][nt][0], acc[mt][nt][1]);
            *(__half2*)(XSs + (r0+8)*264 + col) =
                __floats2half2_rn(acc[mt][nt][2], acc[mt][nt][3]);
        }
    }
    __syncthreads();

    float a2[2][8][4];
    #pragma unroll
    for (int mt = 0; mt < 2; mt++)
        #pragma unroll
        for (int nt = 0; nt < 8; nt++)
            #pragma unroll
            for (int q = 0; q < 4; q++) a2[mt][nt][q] = 0.f;

    #pragma unroll
    for (int kk = 0; kk < 4; kk++) {
        uint32_t af[2][4];
        #pragma unroll
        for (int mt = 0; mt < 2; mt++)
            ldsm4(af[mt], XSs + (wr*32 + mt*16 + (lane & 15)) * 264
                              + wc*64 + kk*16 + ((lane >> 4) << 3));
        #pragma unroll
        for (int g = 0; g < 4; g++) {
            uint32_t r[4];
            ldsm4(r, PWs + (g*16 + (lane & 15)) * 72
                         + kk*16 + ((lane >> 4) << 3));
            #pragma unroll
            for (int mt = 0; mt < 2; mt++) {
                mma8(a2[mt][2*g],   af[mt], r[0], r[2]);
                mma8(a2[mt][2*g+1], af[mt], r[1], r[3]);
            }
        }
    }

    #pragma unroll
    for (int mt = 0; mt < 2; mt++) {
        int r0 = wr*32 + mt*16 + (lane >> 2);
        #pragma unroll
        for (int nt = 0; nt < 8; nt++) {
            int co = nt*8 + 2*(lane & 3);
            float b0 = pbs[co], b1 = pbs[co + 1];
            float* o0 = out + ((size_t)(b*256 + s0 + r0) * 256
                               + h*32 + j0 + wc) * 64 + co;
            float* o1 = out + ((size_t)(b*256 + s0 + r0 + 8) * 256
                               + h*32 + j0 + wc) * 64 + co;
            *(float2*)o0 = make_float2(a2[mt][nt][0] + b0, a2[mt][nt][1] + b1);
            *(float2*)o1 = make_float2(a2[mt][nt][2] + b0, a2[mt][nt][3] + b1);
        }
    }
}

// ---------------------------------------------------------------------------
extern "C" void kernel_launch(void* const* d_in, const int* in_sizes, int n_in,
                              void* d_out, int out_size)
{
    const float* x      = (const float*)d_in[0];
    const float* qkv_w  = (const float*)d_in[1];
    const float* qkv_b  = (const float*)d_in[2];
    const float* proj_w = (const float*)d_in[3];
    const float* proj_b = (const float*)d_in[4];
    const float* t1     = (const float*)d_in[5];
    const float* t2     = (const float*)d_in[6];
    float* out = (float*)d_out;

    const int smem1 = 73728 + 256*4 + 64;                            // ~74.8 KB
    const int smem2 = (3*11264 + 3*22528) * 2 + 256 * 4;             // ~203.8 KB
    const int smem3 = (3*5120*2 + 3*8448*2 + 64*72) * 2 + 64 * 4;    // ~172.3 KB

    cudaFuncSetAttribute((const void*)k_qkv,
                         cudaFuncAttributeMaxDynamicSharedMemorySize, smem1);
    cudaFuncSetAttribute((const void*)k_attn,
                         cudaFuncAttributeMaxDynamicSharedMemorySize, smem2);
    cudaFuncSetAttribute((const void*)k_av,
                         cudaFuncAttributeMaxDynamicSharedMemorySize, smem3);

    k_cvt <<<64, 256>>>(qkv_w, proj_w);
    k_qkv <<<dim3(2048, 2), 512, smem1>>>(x, qkv_b);
    k_attn<<<dim3(64, 2),   512, smem2>>>(t1, t2);
    k_av  <<<dim3(64, 16),  512, smem3>>>(proj_b, out);
}